// round 10
// baseline (speedup 1.0000x reference)
#include <cuda_runtime.h>

#define Nn      100000
#define Ee      1600000
#define IND     128
#define HID     64
#define NC      40
#define KL      3

// Scratch (allocation-free rule: __device__ globals)
__device__ float g_h [Nn * HID];
__device__ float g_h2[Nn * HID];
__device__ float g_agg[Nn * HID];

// ---------- packed f32x2 helpers (Blackwell sm_103a) ----------
__device__ __forceinline__ unsigned long long pack2_dup(float v) {
    unsigned long long r;
    asm("mov.b64 %0, {%1, %2};" : "=l"(r) : "f"(v), "f"(v));
    return r;
}
__device__ __forceinline__ void fma2(unsigned long long& d,
                                     unsigned long long a,
                                     unsigned long long b) {
    asm("fma.rn.f32x2 %0, %1, %2, %0;" : "+l"(d) : "l"(a), "l"(b));
}
__device__ __forceinline__ float2 unpack2(unsigned long long v) {
    float2 r;
    asm("mov.b64 {%0, %1}, %2;" : "=f"(r.x), "=f"(r.y) : "l"(v));
    return r;
}

// ---------- GEMM 1: h = relu(x @ W_in + b_in), x [N,128], W [128,64] ----------
__global__ __launch_bounds__(128) void gemm_in_kernel(
    const float* __restrict__ x, const float* __restrict__ W,
    const float* __restrict__ b, float* __restrict__ out)
{
    __shared__ __align__(16) float sW[IND * HID];   // 32 KB
    for (int i = threadIdx.x; i < IND * HID; i += 128) sW[i] = W[i];
    __syncthreads();

    int row = blockIdx.x * 128 + threadIdx.x;
    if (row >= Nn) return;

    unsigned long long acc[HID / 2];
    #pragma unroll
    for (int p = 0; p < HID / 2; p++) acc[p] = 0ull;

    const float4* x4 = reinterpret_cast<const float4*>(x) + (size_t)row * (IND / 4);
    #pragma unroll 2
    for (int kc = 0; kc < IND / 4; kc++) {
        float4 xv = __ldg(&x4[kc]);
        float zz[4] = {xv.x, xv.y, xv.z, xv.w};
        #pragma unroll
        for (int kk = 0; kk < 4; kk++) {
            int k = kc * 4 + kk;
            unsigned long long a2 = pack2_dup(zz[kk]);
            const ulonglong2* w2 = reinterpret_cast<const ulonglong2*>(&sW[k * HID]);
            #pragma unroll
            for (int p = 0; p < HID / 4; p++) {
                ulonglong2 w = w2[p];
                fma2(acc[2 * p + 0], a2, w.x);
                fma2(acc[2 * p + 1], a2, w.y);
            }
        }
    }

    float4* o4 = reinterpret_cast<float4*>(out) + (size_t)row * (HID / 4);
    #pragma unroll
    for (int q = 0; q < HID / 4; q++) {
        float2 t0 = unpack2(acc[2 * q + 0]);
        float2 t1 = unpack2(acc[2 * q + 1]);
        float4 o;
        o.x = fmaxf(t0.x + __ldg(&b[4 * q + 0]), 0.f);
        o.y = fmaxf(t0.y + __ldg(&b[4 * q + 1]), 0.f);
        o.z = fmaxf(t1.x + __ldg(&b[4 * q + 2]), 0.f);
        o.w = fmaxf(t1.y + __ldg(&b[4 * q + 3]), 0.f);
        o4[q] = o;
    }
}

// ---------- Scatter: agg[dst] += h[src], per edge 64 floats ----------
// 16 lanes per edge, one float4 each -> coalesced gather + vector red to L2.
__global__ __launch_bounds__(256) void scatter_kernel(
    const int* __restrict__ ei, const float* __restrict__ h,
    float* __restrict__ agg)
{
    int gid = blockIdx.x * 256 + threadIdx.x;
    int e = gid >> 4;
    int c = gid & 15;
    if (e >= Ee) return;
    int src = __ldg(&ei[e]);
    int dst = __ldg(&ei[Ee + e]);
    const float4* h4 = reinterpret_cast<const float4*>(h);
    float4 v = __ldg(&h4[src * 16 + c]);
    const float4* a = reinterpret_cast<const float4*>(agg) + (dst * 16 + c);
    asm volatile("red.global.add.v4.f32 [%0], {%1, %2, %3, %4};"
                 :: "l"(a), "f"(v.x), "f"(v.y), "f"(v.z), "f"(v.w)
                 : "memory");
}

// ---------- GEMM hidden: h2 = relu((h + agg) @ W + b), W [64,64] ----------
__global__ __launch_bounds__(128) void gemm_hid_kernel(
    const float* __restrict__ hin, const float* __restrict__ agg,
    const float* __restrict__ W, const float* __restrict__ b,
    float* __restrict__ out)
{
    __shared__ __align__(16) float sW[HID * HID];   // 16 KB
    for (int i = threadIdx.x; i < HID * HID; i += 128) sW[i] = W[i];
    __syncthreads();

    int row = blockIdx.x * 128 + threadIdx.x;
    if (row >= Nn) return;

    unsigned long long acc[HID / 2];
    #pragma unroll
    for (int p = 0; p < HID / 2; p++) acc[p] = 0ull;

    const float4* h4 = reinterpret_cast<const float4*>(hin) + (size_t)row * (HID / 4);
    const float4* a4 = reinterpret_cast<const float4*>(agg) + (size_t)row * (HID / 4);
    #pragma unroll 2
    for (int kc = 0; kc < HID / 4; kc++) {
        float4 hv = __ldg(&h4[kc]);
        float4 av = __ldg(&a4[kc]);
        float zz[4] = {hv.x + av.x, hv.y + av.y, hv.z + av.z, hv.w + av.w};
        #pragma unroll
        for (int kk = 0; kk < 4; kk++) {
            int k = kc * 4 + kk;
            unsigned long long a2 = pack2_dup(zz[kk]);
            const ulonglong2* w2 = reinterpret_cast<const ulonglong2*>(&sW[k * HID]);
            #pragma unroll
            for (int p = 0; p < HID / 4; p++) {
                ulonglong2 w = w2[p];
                fma2(acc[2 * p + 0], a2, w.x);
                fma2(acc[2 * p + 1], a2, w.y);
            }
        }
    }

    float4* o4 = reinterpret_cast<float4*>(out) + (size_t)row * (HID / 4);
    #pragma unroll
    for (int q = 0; q < HID / 4; q++) {
        float2 t0 = unpack2(acc[2 * q + 0]);
        float2 t1 = unpack2(acc[2 * q + 1]);
        float4 o;
        o.x = fmaxf(t0.x + __ldg(&b[4 * q + 0]), 0.f);
        o.y = fmaxf(t0.y + __ldg(&b[4 * q + 1]), 0.f);
        o.z = fmaxf(t1.x + __ldg(&b[4 * q + 2]), 0.f);
        o.w = fmaxf(t1.y + __ldg(&b[4 * q + 3]), 0.f);
        o4[q] = o;
    }
}

// ---------- GEMM out: out = h @ W_cls + b_cls, W [64,40], no relu ----------
__global__ __launch_bounds__(128) void gemm_out_kernel(
    const float* __restrict__ hin, const float* __restrict__ W,
    const float* __restrict__ b, float* __restrict__ out)
{
    __shared__ __align__(16) float sW[HID * NC];    // 10 KB
    for (int i = threadIdx.x; i < HID * NC; i += 128) sW[i] = W[i];
    __syncthreads();

    int row = blockIdx.x * 128 + threadIdx.x;
    if (row >= Nn) return;

    unsigned long long acc[NC / 2];
    #pragma unroll
    for (int p = 0; p < NC / 2; p++) acc[p] = 0ull;

    const float4* h4 = reinterpret_cast<const float4*>(hin) + (size_t)row * (HID / 4);
    #pragma unroll 2
    for (int kc = 0; kc < HID / 4; kc++) {
        float4 hv = __ldg(&h4[kc]);
        float zz[4] = {hv.x, hv.y, hv.z, hv.w};
        #pragma unroll
        for (int kk = 0; kk < 4; kk++) {
            int k = kc * 4 + kk;
            unsigned long long a2 = pack2_dup(zz[kk]);
            // row of W: 40 floats = 160 B, 16B-aligned
            const ulonglong2* w2 = reinterpret_cast<const ulonglong2*>(&sW[k * NC]);
            #pragma unroll
            for (int p = 0; p < NC / 4; p++) {
                ulonglong2 w = w2[p];
                fma2(acc[2 * p + 0], a2, w.x);
                fma2(acc[2 * p + 1], a2, w.y);
            }
        }
    }

    float4* o4 = reinterpret_cast<float4*>(out) + (size_t)row * (NC / 4);
    #pragma unroll
    for (int q = 0; q < NC / 4; q++) {
        float2 t0 = unpack2(acc[2 * q + 0]);
        float2 t1 = unpack2(acc[2 * q + 1]);
        float4 o;
        o.x = t0.x + __ldg(&b[4 * q + 0]);
        o.y = t0.y + __ldg(&b[4 * q + 1]);
        o.z = t1.x + __ldg(&b[4 * q + 2]);
        o.w = t1.y + __ldg(&b[4 * q + 3]);
        o4[q] = o;
    }
}

extern "C" void kernel_launch(void* const* d_in, const int* in_sizes, int n_in,
                              void* d_out, int out_size)
{
    const float* x        = (const float*)d_in[0];
    const int*   ei       = (const int*)  d_in[1];
    const float* W_in     = (const float*)d_in[2];
    const float* b_in     = (const float*)d_in[3];
    const float* W_layers = (const float*)d_in[4];
    const float* b_layers = (const float*)d_in[5];
    const float* W_cls    = (const float*)d_in[6];
    const float* b_cls    = (const float*)d_in[7];
    float* out = (float*)d_out;

    float *h, *h2, *agg;
    cudaGetSymbolAddress((void**)&h,   g_h);
    cudaGetSymbolAddress((void**)&h2,  g_h2);
    cudaGetSymbolAddress((void**)&agg, g_agg);

    const int gemm_blocks = (Nn + 127) / 128;
    const long long sc_threads = (long long)Ee * 16;
    const int sc_blocks = (int)((sc_threads + 255) / 256);

    gemm_in_kernel<<<gemm_blocks, 128>>>(x, W_in, b_in, h);

    for (int i = 0; i < KL; i++) {
        cudaMemsetAsync(agg, 0, (size_t)Nn * HID * sizeof(float));
        scatter_kernel<<<sc_blocks, 256>>>(ei, h, agg);
        gemm_hid_kernel<<<gemm_blocks, 128>>>(
            h, agg, W_layers + (size_t)i * HID * HID, b_layers + (size_t)i * HID, h2);
        float* t = h; h = h2; h2 = t;
    }

    gemm_out_kernel<<<gemm_blocks, 128>>>(h, W_cls, b_cls, out);
}

// round 11
// speedup vs baseline: 1.0062x; 1.0062x over previous
#include <cuda_runtime.h>

#define Nn      100000
#define Ee      1600000
#define IND     128
#define HID     64
#define NC      40
#define KL      3

// Scratch (allocation-free rule: __device__ globals)
__device__ float g_h [Nn * HID];
__device__ float g_h2[Nn * HID];
__device__ float g_agg[Nn * HID];

// ---------- packed f32x2 helpers (Blackwell sm_103a) ----------
__device__ __forceinline__ unsigned long long pack2_dup(float v) {
    unsigned long long r;
    asm("mov.b64 %0, {%1, %2};" : "=l"(r) : "f"(v), "f"(v));
    return r;
}
__device__ __forceinline__ void fma2(unsigned long long& d,
                                     unsigned long long a,
                                     unsigned long long b) {
    asm("fma.rn.f32x2 %0, %1, %2, %0;" : "+l"(d) : "l"(a), "l"(b));
}
__device__ __forceinline__ float2 unpack2(unsigned long long v) {
    float2 r;
    asm("mov.b64 {%0, %1}, %2;" : "=f"(r.x), "=f"(r.y) : "l"(v));
    return r;
}

// ---------- GEMM 1: h = relu(x @ W_in + b_in), x [N,128], W [128,64] ----------
__global__ __launch_bounds__(128) void gemm_in_kernel(
    const float* __restrict__ x, const float* __restrict__ W,
    const float* __restrict__ b, float* __restrict__ out)
{
    __shared__ __align__(16) float sW[IND * HID];   // 32 KB
    for (int i = threadIdx.x; i < IND * HID; i += 128) sW[i] = W[i];
    __syncthreads();

    int row = blockIdx.x * 128 + threadIdx.x;
    if (row >= Nn) return;

    unsigned long long acc[HID / 2];
    #pragma unroll
    for (int p = 0; p < HID / 2; p++) acc[p] = 0ull;

    const float4* x4 = reinterpret_cast<const float4*>(x) + (size_t)row * (IND / 4);
    #pragma unroll 2
    for (int kc = 0; kc < IND / 4; kc++) {
        float4 xv = __ldg(&x4[kc]);
        float zz[4] = {xv.x, xv.y, xv.z, xv.w};
        #pragma unroll
        for (int kk = 0; kk < 4; kk++) {
            int k = kc * 4 + kk;
            unsigned long long a2 = pack2_dup(zz[kk]);
            const ulonglong2* w2 = reinterpret_cast<const ulonglong2*>(&sW[k * HID]);
            #pragma unroll
            for (int p = 0; p < HID / 4; p++) {
                ulonglong2 w = w2[p];
                fma2(acc[2 * p + 0], a2, w.x);
                fma2(acc[2 * p + 1], a2, w.y);
            }
        }
    }

    float4* o4 = reinterpret_cast<float4*>(out) + (size_t)row * (HID / 4);
    #pragma unroll
    for (int q = 0; q < HID / 4; q++) {
        float2 t0 = unpack2(acc[2 * q + 0]);
        float2 t1 = unpack2(acc[2 * q + 1]);
        float4 o;
        o.x = fmaxf(t0.x + __ldg(&b[4 * q + 0]), 0.f);
        o.y = fmaxf(t0.y + __ldg(&b[4 * q + 1]), 0.f);
        o.z = fmaxf(t1.x + __ldg(&b[4 * q + 2]), 0.f);
        o.w = fmaxf(t1.y + __ldg(&b[4 * q + 3]), 0.f);
        o4[q] = o;
    }
}

// ---------- Scatter: agg[dst] += h[src], per edge 64 floats ----------
// 16 lanes per edge, one float4 each -> coalesced gather + vector red to L2.
__global__ __launch_bounds__(256) void scatter_kernel(
    const int* __restrict__ ei, const float* __restrict__ h,
    float* __restrict__ agg)
{
    int gid = blockIdx.x * 256 + threadIdx.x;
    int e = gid >> 4;
    int c = gid & 15;
    if (e >= Ee) return;
    int src = __ldg(&ei[e]);
    int dst = __ldg(&ei[Ee + e]);
    const float4* h4 = reinterpret_cast<const float4*>(h);
    float4 v = __ldg(&h4[src * 16 + c]);
    const float4* a = reinterpret_cast<const float4*>(agg) + (dst * 16 + c);
    asm volatile("red.global.add.v4.f32 [%0], {%1, %2, %3, %4};"
                 :: "l"(a), "f"(v.x), "f"(v.y), "f"(v.z), "f"(v.w)
                 : "memory");
}

// ---------- GEMM hidden: h2 = relu((h + agg) @ W + b), W [64,64] ----------
__global__ __launch_bounds__(128) void gemm_hid_kernel(
    const float* __restrict__ hin, const float* __restrict__ agg,
    const float* __restrict__ W, const float* __restrict__ b,
    float* __restrict__ out)
{
    __shared__ __align__(16) float sW[HID * HID];   // 16 KB
    for (int i = threadIdx.x; i < HID * HID; i += 128) sW[i] = W[i];
    __syncthreads();

    int row = blockIdx.x * 128 + threadIdx.x;
    if (row >= Nn) return;

    unsigned long long acc[HID / 2];
    #pragma unroll
    for (int p = 0; p < HID / 2; p++) acc[p] = 0ull;

    const float4* h4 = reinterpret_cast<const float4*>(hin) + (size_t)row * (HID / 4);
    const float4* a4 = reinterpret_cast<const float4*>(agg) + (size_t)row * (HID / 4);
    #pragma unroll 2
    for (int kc = 0; kc < HID / 4; kc++) {
        float4 hv = __ldg(&h4[kc]);
        float4 av = __ldg(&a4[kc]);
        float zz[4] = {hv.x + av.x, hv.y + av.y, hv.z + av.z, hv.w + av.w};
        #pragma unroll
        for (int kk = 0; kk < 4; kk++) {
            int k = kc * 4 + kk;
            unsigned long long a2 = pack2_dup(zz[kk]);
            const ulonglong2* w2 = reinterpret_cast<const ulonglong2*>(&sW[k * HID]);
            #pragma unroll
            for (int p = 0; p < HID / 4; p++) {
                ulonglong2 w = w2[p];
                fma2(acc[2 * p + 0], a2, w.x);
                fma2(acc[2 * p + 1], a2, w.y);
            }
        }
    }

    float4* o4 = reinterpret_cast<float4*>(out) + (size_t)row * (HID / 4);
    #pragma unroll
    for (int q = 0; q < HID / 4; q++) {
        float2 t0 = unpack2(acc[2 * q + 0]);
        float2 t1 = unpack2(acc[2 * q + 1]);
        float4 o;
        o.x = fmaxf(t0.x + __ldg(&b[4 * q + 0]), 0.f);
        o.y = fmaxf(t0.y + __ldg(&b[4 * q + 1]), 0.f);
        o.z = fmaxf(t1.x + __ldg(&b[4 * q + 2]), 0.f);
        o.w = fmaxf(t1.y + __ldg(&b[4 * q + 3]), 0.f);
        o4[q] = o;
    }
}

// ---------- GEMM out: out = h @ W_cls + b_cls, W [64,40], no relu ----------
__global__ __launch_bounds__(128) void gemm_out_kernel(
    const float* __restrict__ hin, const float* __restrict__ W,
    const float* __restrict__ b, float* __restrict__ out)
{
    __shared__ __align__(16) float sW[HID * NC];    // 10 KB
    for (int i = threadIdx.x; i < HID * NC; i += 128) sW[i] = W[i];
    __syncthreads();

    int row = blockIdx.x * 128 + threadIdx.x;
    if (row >= Nn) return;

    unsigned long long acc[NC / 2];
    #pragma unroll
    for (int p = 0; p < NC / 2; p++) acc[p] = 0ull;

    const float4* h4 = reinterpret_cast<const float4*>(hin) + (size_t)row * (HID / 4);
    #pragma unroll 2
    for (int kc = 0; kc < HID / 4; kc++) {
        float4 hv = __ldg(&h4[kc]);
        float zz[4] = {hv.x, hv.y, hv.z, hv.w};
        #pragma unroll
        for (int kk = 0; kk < 4; kk++) {
            int k = kc * 4 + kk;
            unsigned long long a2 = pack2_dup(zz[kk]);
            // row of W: 40 floats = 160 B, 16B-aligned
            const ulonglong2* w2 = reinterpret_cast<const ulonglong2*>(&sW[k * NC]);
            #pragma unroll
            for (int p = 0; p < NC / 4; p++) {
                ulonglong2 w = w2[p];
                fma2(acc[2 * p + 0], a2, w.x);
                fma2(acc[2 * p + 1], a2, w.y);
            }
        }
    }

    float4* o4 = reinterpret_cast<float4*>(out) + (size_t)row * (NC / 4);
    #pragma unroll
    for (int q = 0; q < NC / 4; q++) {
        float2 t0 = unpack2(acc[2 * q + 0]);
        float2 t1 = unpack2(acc[2 * q + 1]);
        float4 o;
        o.x = t0.x + __ldg(&b[4 * q + 0]);
        o.y = t0.y + __ldg(&b[4 * q + 1]);
        o.z = t1.x + __ldg(&b[4 * q + 2]);
        o.w = t1.y + __ldg(&b[4 * q + 3]);
        o4[q] = o;
    }
}

extern "C" void kernel_launch(void* const* d_in, const int* in_sizes, int n_in,
                              void* d_out, int out_size)
{
    const float* x        = (const float*)d_in[0];
    const int*   ei       = (const int*)  d_in[1];
    const float* W_in     = (const float*)d_in[2];
    const float* b_in     = (const float*)d_in[3];
    const float* W_layers = (const float*)d_in[4];
    const float* b_layers = (const float*)d_in[5];
    const float* W_cls    = (const float*)d_in[6];
    const float* b_cls    = (const float*)d_in[7];
    float* out = (float*)d_out;

    float *h, *h2, *agg;
    cudaGetSymbolAddress((void**)&h,   g_h);
    cudaGetSymbolAddress((void**)&h2,  g_h2);
    cudaGetSymbolAddress((void**)&agg, g_agg);

    const int gemm_blocks = (Nn + 127) / 128;
    const long long sc_threads = (long long)Ee * 16;
    const int sc_blocks = (int)((sc_threads + 255) / 256);

    gemm_in_kernel<<<gemm_blocks, 128>>>(x, W_in, b_in, h);

    for (int i = 0; i < KL; i++) {
        cudaMemsetAsync(agg, 0, (size_t)Nn * HID * sizeof(float));
        scatter_kernel<<<sc_blocks, 256>>>(ei, h, agg);
        gemm_hid_kernel<<<gemm_blocks, 128>>>(
            h, agg, W_layers + (size_t)i * HID * HID, b_layers + (size_t)i * HID, h2);
        float* t = h; h = h2; h2 = t;
    }

    gemm_out_kernel<<<gemm_blocks, 128>>>(h, W_cls, b_cls, out);
}

// round 12
// speedup vs baseline: 1.0076x; 1.0014x over previous
#include <cuda_runtime.h>

#define Nn      100000
#define Ee      1600000
#define IND     128
#define HID     64
#define NC      40
#define KL      3

// Scratch (allocation-free rule: __device__ globals)
__device__ float g_h [Nn * HID];
__device__ float g_h2[Nn * HID];
__device__ float g_agg[Nn * HID];

// ---------- packed f32x2 helpers (Blackwell sm_103a) ----------
__device__ __forceinline__ unsigned long long pack2_dup(float v) {
    unsigned long long r;
    asm("mov.b64 %0, {%1, %2};" : "=l"(r) : "f"(v), "f"(v));
    return r;
}
__device__ __forceinline__ void fma2(unsigned long long& d,
                                     unsigned long long a,
                                     unsigned long long b) {
    asm("fma.rn.f32x2 %0, %1, %2, %0;" : "+l"(d) : "l"(a), "l"(b));
}
__device__ __forceinline__ float2 unpack2(unsigned long long v) {
    float2 r;
    asm("mov.b64 {%0, %1}, %2;" : "=f"(r.x), "=f"(r.y) : "l"(v));
    return r;
}

// ---------- GEMM 1: h = relu(x @ W_in + b_in), x [N,128], W [128,64] ----------
__global__ __launch_bounds__(128) void gemm_in_kernel(
    const float* __restrict__ x, const float* __restrict__ W,
    const float* __restrict__ b, float* __restrict__ out)
{
    __shared__ __align__(16) float sW[IND * HID];   // 32 KB
    for (int i = threadIdx.x; i < IND * HID; i += 128) sW[i] = W[i];
    __syncthreads();

    int row = blockIdx.x * 128 + threadIdx.x;
    if (row >= Nn) return;

    unsigned long long acc[HID / 2];
    #pragma unroll
    for (int p = 0; p < HID / 2; p++) acc[p] = 0ull;

    const float4* x4 = reinterpret_cast<const float4*>(x) + (size_t)row * (IND / 4);
    #pragma unroll 2
    for (int kc = 0; kc < IND / 4; kc++) {
        float4 xv = __ldg(&x4[kc]);
        float zz[4] = {xv.x, xv.y, xv.z, xv.w};
        #pragma unroll
        for (int kk = 0; kk < 4; kk++) {
            int k = kc * 4 + kk;
            unsigned long long a2 = pack2_dup(zz[kk]);
            const ulonglong2* w2 = reinterpret_cast<const ulonglong2*>(&sW[k * HID]);
            #pragma unroll
            for (int p = 0; p < HID / 4; p++) {
                ulonglong2 w = w2[p];
                fma2(acc[2 * p + 0], a2, w.x);
                fma2(acc[2 * p + 1], a2, w.y);
            }
        }
    }

    float4* o4 = reinterpret_cast<float4*>(out) + (size_t)row * (HID / 4);
    #pragma unroll
    for (int q = 0; q < HID / 4; q++) {
        float2 t0 = unpack2(acc[2 * q + 0]);
        float2 t1 = unpack2(acc[2 * q + 1]);
        float4 o;
        o.x = fmaxf(t0.x + __ldg(&b[4 * q + 0]), 0.f);
        o.y = fmaxf(t0.y + __ldg(&b[4 * q + 1]), 0.f);
        o.z = fmaxf(t1.x + __ldg(&b[4 * q + 2]), 0.f);
        o.w = fmaxf(t1.y + __ldg(&b[4 * q + 3]), 0.f);
        o4[q] = o;
    }
}

// ---------- Scatter: agg[dst] += h[src], per edge 64 floats ----------
// 16 lanes per edge, one float4 each -> coalesced gather + vector red to L2.
__global__ __launch_bounds__(256) void scatter_kernel(
    const int* __restrict__ ei, const float* __restrict__ h,
    float* __restrict__ agg)
{
    int gid = blockIdx.x * 256 + threadIdx.x;
    int e = gid >> 4;
    int c = gid & 15;
    if (e >= Ee) return;
    int src = __ldg(&ei[e]);
    int dst = __ldg(&ei[Ee + e]);
    const float4* h4 = reinterpret_cast<const float4*>(h);
    float4 v = __ldg(&h4[src * 16 + c]);
    const float4* a = reinterpret_cast<const float4*>(agg) + (dst * 16 + c);
    asm volatile("red.global.add.v4.f32 [%0], {%1, %2, %3, %4};"
                 :: "l"(a), "f"(v.x), "f"(v.y), "f"(v.z), "f"(v.w)
                 : "memory");
}

// ---------- GEMM hidden: h2 = relu((h + agg) @ W + b), W [64,64] ----------
__global__ __launch_bounds__(128) void gemm_hid_kernel(
    const float* __restrict__ hin, const float* __restrict__ agg,
    const float* __restrict__ W, const float* __restrict__ b,
    float* __restrict__ out)
{
    __shared__ __align__(16) float sW[HID * HID];   // 16 KB
    for (int i = threadIdx.x; i < HID * HID; i += 128) sW[i] = W[i];
    __syncthreads();

    int row = blockIdx.x * 128 + threadIdx.x;
    if (row >= Nn) return;

    unsigned long long acc[HID / 2];
    #pragma unroll
    for (int p = 0; p < HID / 2; p++) acc[p] = 0ull;

    const float4* h4 = reinterpret_cast<const float4*>(hin) + (size_t)row * (HID / 4);
    const float4* a4 = reinterpret_cast<const float4*>(agg) + (size_t)row * (HID / 4);
    #pragma unroll 2
    for (int kc = 0; kc < HID / 4; kc++) {
        float4 hv = __ldg(&h4[kc]);
        float4 av = __ldg(&a4[kc]);
        float zz[4] = {hv.x + av.x, hv.y + av.y, hv.z + av.z, hv.w + av.w};
        #pragma unroll
        for (int kk = 0; kk < 4; kk++) {
            int k = kc * 4 + kk;
            unsigned long long a2 = pack2_dup(zz[kk]);
            const ulonglong2* w2 = reinterpret_cast<const ulonglong2*>(&sW[k * HID]);
            #pragma unroll
            for (int p = 0; p < HID / 4; p++) {
                ulonglong2 w = w2[p];
                fma2(acc[2 * p + 0], a2, w.x);
                fma2(acc[2 * p + 1], a2, w.y);
            }
        }
    }

    float4* o4 = reinterpret_cast<float4*>(out) + (size_t)row * (HID / 4);
    #pragma unroll
    for (int q = 0; q < HID / 4; q++) {
        float2 t0 = unpack2(acc[2 * q + 0]);
        float2 t1 = unpack2(acc[2 * q + 1]);
        float4 o;
        o.x = fmaxf(t0.x + __ldg(&b[4 * q + 0]), 0.f);
        o.y = fmaxf(t0.y + __ldg(&b[4 * q + 1]), 0.f);
        o.z = fmaxf(t1.x + __ldg(&b[4 * q + 2]), 0.f);
        o.w = fmaxf(t1.y + __ldg(&b[4 * q + 3]), 0.f);
        o4[q] = o;
    }
}

// ---------- GEMM out: out = h @ W_cls + b_cls, W [64,40], no relu ----------
__global__ __launch_bounds__(128) void gemm_out_kernel(
    const float* __restrict__ hin, const float* __restrict__ W,
    const float* __restrict__ b, float* __restrict__ out)
{
    __shared__ __align__(16) float sW[HID * NC];    // 10 KB
    for (int i = threadIdx.x; i < HID * NC; i += 128) sW[i] = W[i];
    __syncthreads();

    int row = blockIdx.x * 128 + threadIdx.x;
    if (row >= Nn) return;

    unsigned long long acc[NC / 2];
    #pragma unroll
    for (int p = 0; p < NC / 2; p++) acc[p] = 0ull;

    const float4* h4 = reinterpret_cast<const float4*>(hin) + (size_t)row * (HID / 4);
    #pragma unroll 2
    for (int kc = 0; kc < HID / 4; kc++) {
        float4 hv = __ldg(&h4[kc]);
        float zz[4] = {hv.x, hv.y, hv.z, hv.w};
        #pragma unroll
        for (int kk = 0; kk < 4; kk++) {
            int k = kc * 4 + kk;
            unsigned long long a2 = pack2_dup(zz[kk]);
            // row of W: 40 floats = 160 B, 16B-aligned
            const ulonglong2* w2 = reinterpret_cast<const ulonglong2*>(&sW[k * NC]);
            #pragma unroll
            for (int p = 0; p < NC / 4; p++) {
                ulonglong2 w = w2[p];
                fma2(acc[2 * p + 0], a2, w.x);
                fma2(acc[2 * p + 1], a2, w.y);
            }
        }
    }

    float4* o4 = reinterpret_cast<float4*>(out) + (size_t)row * (NC / 4);
    #pragma unroll
    for (int q = 0; q < NC / 4; q++) {
        float2 t0 = unpack2(acc[2 * q + 0]);
        float2 t1 = unpack2(acc[2 * q + 1]);
        float4 o;
        o.x = t0.x + __ldg(&b[4 * q + 0]);
        o.y = t0.y + __ldg(&b[4 * q + 1]);
        o.z = t1.x + __ldg(&b[4 * q + 2]);
        o.w = t1.y + __ldg(&b[4 * q + 3]);
        o4[q] = o;
    }
}

extern "C" void kernel_launch(void* const* d_in, const int* in_sizes, int n_in,
                              void* d_out, int out_size)
{
    const float* x        = (const float*)d_in[0];
    const int*   ei       = (const int*)  d_in[1];
    const float* W_in     = (const float*)d_in[2];
    const float* b_in     = (const float*)d_in[3];
    const float* W_layers = (const float*)d_in[4];
    const float* b_layers = (const float*)d_in[5];
    const float* W_cls    = (const float*)d_in[6];
    const float* b_cls    = (const float*)d_in[7];
    float* out = (float*)d_out;

    float *h, *h2, *agg;
    cudaGetSymbolAddress((void**)&h,   g_h);
    cudaGetSymbolAddress((void**)&h2,  g_h2);
    cudaGetSymbolAddress((void**)&agg, g_agg);

    const int gemm_blocks = (Nn + 127) / 128;
    const long long sc_threads = (long long)Ee * 16;
    const int sc_blocks = (int)((sc_threads + 255) / 256);

    gemm_in_kernel<<<gemm_blocks, 128>>>(x, W_in, b_in, h);

    for (int i = 0; i < KL; i++) {
        cudaMemsetAsync(agg, 0, (size_t)Nn * HID * sizeof(float));
        scatter_kernel<<<sc_blocks, 256>>>(ei, h, agg);
        gemm_hid_kernel<<<gemm_blocks, 128>>>(
            h, agg, W_layers + (size_t)i * HID * HID, b_layers + (size_t)i * HID, h2);
        float* t = h; h = h2; h2 = t;
    }

    gemm_out_kernel<<<gemm_blocks, 128>>>(h, W_cls, b_cls, out);
}

// round 13
// speedup vs baseline: 1.0104x; 1.0028x over previous
#include <cuda_runtime.h>

#define Nn      100000
#define Ee      1600000
#define IND     128
#define HID     64
#define NC      40
#define KL      3

// Scratch (allocation-free rule: __device__ globals)
__device__ float g_h [Nn * HID];
__device__ float g_h2[Nn * HID];
__device__ float g_agg[Nn * HID];

// ---------- packed f32x2 helpers (Blackwell sm_103a) ----------
__device__ __forceinline__ unsigned long long pack2_dup(float v) {
    unsigned long long r;
    asm("mov.b64 %0, {%1, %2};" : "=l"(r) : "f"(v), "f"(v));
    return r;
}
__device__ __forceinline__ void fma2(unsigned long long& d,
                                     unsigned long long a,
                                     unsigned long long b) {
    asm("fma.rn.f32x2 %0, %1, %2, %0;" : "+l"(d) : "l"(a), "l"(b));
}
__device__ __forceinline__ float2 unpack2(unsigned long long v) {
    float2 r;
    asm("mov.b64 {%0, %1}, %2;" : "=f"(r.x), "=f"(r.y) : "l"(v));
    return r;
}

// ---------- GEMM 1: h = relu(x @ W_in + b_in), x [N,128], W [128,64] ----------
__global__ __launch_bounds__(128) void gemm_in_kernel(
    const float* __restrict__ x, const float* __restrict__ W,
    const float* __restrict__ b, float* __restrict__ out)
{
    __shared__ __align__(16) float sW[IND * HID];   // 32 KB
    for (int i = threadIdx.x; i < IND * HID; i += 128) sW[i] = W[i];
    __syncthreads();

    int row = blockIdx.x * 128 + threadIdx.x;
    if (row >= Nn) return;

    unsigned long long acc[HID / 2];
    #pragma unroll
    for (int p = 0; p < HID / 2; p++) acc[p] = 0ull;

    const float4* x4 = reinterpret_cast<const float4*>(x) + (size_t)row * (IND / 4);
    #pragma unroll 2
    for (int kc = 0; kc < IND / 4; kc++) {
        float4 xv = __ldg(&x4[kc]);
        float zz[4] = {xv.x, xv.y, xv.z, xv.w};
        #pragma unroll
        for (int kk = 0; kk < 4; kk++) {
            int k = kc * 4 + kk;
            unsigned long long a2 = pack2_dup(zz[kk]);
            const ulonglong2* w2 = reinterpret_cast<const ulonglong2*>(&sW[k * HID]);
            #pragma unroll
            for (int p = 0; p < HID / 4; p++) {
                ulonglong2 w = w2[p];
                fma2(acc[2 * p + 0], a2, w.x);
                fma2(acc[2 * p + 1], a2, w.y);
            }
        }
    }

    float4* o4 = reinterpret_cast<float4*>(out) + (size_t)row * (HID / 4);
    #pragma unroll
    for (int q = 0; q < HID / 4; q++) {
        float2 t0 = unpack2(acc[2 * q + 0]);
        float2 t1 = unpack2(acc[2 * q + 1]);
        float4 o;
        o.x = fmaxf(t0.x + __ldg(&b[4 * q + 0]), 0.f);
        o.y = fmaxf(t0.y + __ldg(&b[4 * q + 1]), 0.f);
        o.z = fmaxf(t1.x + __ldg(&b[4 * q + 2]), 0.f);
        o.w = fmaxf(t1.y + __ldg(&b[4 * q + 3]), 0.f);
        o4[q] = o;
    }
}

// ---------- Scatter: agg[dst] += h[src], per edge 64 floats ----------
// 16 lanes per edge, one float4 each -> coalesced gather + vector red to L2.
__global__ __launch_bounds__(256) void scatter_kernel(
    const int* __restrict__ ei, const float* __restrict__ h,
    float* __restrict__ agg)
{
    int gid = blockIdx.x * 256 + threadIdx.x;
    int e = gid >> 4;
    int c = gid & 15;
    if (e >= Ee) return;
    int src = __ldg(&ei[e]);
    int dst = __ldg(&ei[Ee + e]);
    const float4* h4 = reinterpret_cast<const float4*>(h);
    float4 v = __ldg(&h4[src * 16 + c]);
    const float4* a = reinterpret_cast<const float4*>(agg) + (dst * 16 + c);
    asm volatile("red.global.add.v4.f32 [%0], {%1, %2, %3, %4};"
                 :: "l"(a), "f"(v.x), "f"(v.y), "f"(v.z), "f"(v.w)
                 : "memory");
}

// ---------- GEMM hidden: h2 = relu((h + agg) @ W + b), W [64,64] ----------
__global__ __launch_bounds__(128) void gemm_hid_kernel(
    const float* __restrict__ hin, const float* __restrict__ agg,
    const float* __restrict__ W, const float* __restrict__ b,
    float* __restrict__ out)
{
    __shared__ __align__(16) float sW[HID * HID];   // 16 KB
    for (int i = threadIdx.x; i < HID * HID; i += 128) sW[i] = W[i];
    __syncthreads();

    int row = blockIdx.x * 128 + threadIdx.x;
    if (row >= Nn) return;

    unsigned long long acc[HID / 2];
    #pragma unroll
    for (int p = 0; p < HID / 2; p++) acc[p] = 0ull;

    const float4* h4 = reinterpret_cast<const float4*>(hin) + (size_t)row * (HID / 4);
    const float4* a4 = reinterpret_cast<const float4*>(agg) + (size_t)row * (HID / 4);
    #pragma unroll 2
    for (int kc = 0; kc < HID / 4; kc++) {
        float4 hv = __ldg(&h4[kc]);
        float4 av = __ldg(&a4[kc]);
        float zz[4] = {hv.x + av.x, hv.y + av.y, hv.z + av.z, hv.w + av.w};
        #pragma unroll
        for (int kk = 0; kk < 4; kk++) {
            int k = kc * 4 + kk;
            unsigned long long a2 = pack2_dup(zz[kk]);
            const ulonglong2* w2 = reinterpret_cast<const ulonglong2*>(&sW[k * HID]);
            #pragma unroll
            for (int p = 0; p < HID / 4; p++) {
                ulonglong2 w = w2[p];
                fma2(acc[2 * p + 0], a2, w.x);
                fma2(acc[2 * p + 1], a2, w.y);
            }
        }
    }

    float4* o4 = reinterpret_cast<float4*>(out) + (size_t)row * (HID / 4);
    #pragma unroll
    for (int q = 0; q < HID / 4; q++) {
        float2 t0 = unpack2(acc[2 * q + 0]);
        float2 t1 = unpack2(acc[2 * q + 1]);
        float4 o;
        o.x = fmaxf(t0.x + __ldg(&b[4 * q + 0]), 0.f);
        o.y = fmaxf(t0.y + __ldg(&b[4 * q + 1]), 0.f);
        o.z = fmaxf(t1.x + __ldg(&b[4 * q + 2]), 0.f);
        o.w = fmaxf(t1.y + __ldg(&b[4 * q + 3]), 0.f);
        o4[q] = o;
    }
}

// ---------- GEMM out: out = h @ W_cls + b_cls, W [64,40], no relu ----------
__global__ __launch_bounds__(128) void gemm_out_kernel(
    const float* __restrict__ hin, const float* __restrict__ W,
    const float* __restrict__ b, float* __restrict__ out)
{
    __shared__ __align__(16) float sW[HID * NC];    // 10 KB
    for (int i = threadIdx.x; i < HID * NC; i += 128) sW[i] = W[i];
    __syncthreads();

    int row = blockIdx.x * 128 + threadIdx.x;
    if (row >= Nn) return;

    unsigned long long acc[NC / 2];
    #pragma unroll
    for (int p = 0; p < NC / 2; p++) acc[p] = 0ull;

    const float4* h4 = reinterpret_cast<const float4*>(hin) + (size_t)row * (HID / 4);
    #pragma unroll 2
    for (int kc = 0; kc < HID / 4; kc++) {
        float4 hv = __ldg(&h4[kc]);
        float zz[4] = {hv.x, hv.y, hv.z, hv.w};
        #pragma unroll
        for (int kk = 0; kk < 4; kk++) {
            int k = kc * 4 + kk;
            unsigned long long a2 = pack2_dup(zz[kk]);
            // row of W: 40 floats = 160 B, 16B-aligned
            const ulonglong2* w2 = reinterpret_cast<const ulonglong2*>(&sW[k * NC]);
            #pragma unroll
            for (int p = 0; p < NC / 4; p++) {
                ulonglong2 w = w2[p];
                fma2(acc[2 * p + 0], a2, w.x);
                fma2(acc[2 * p + 1], a2, w.y);
            }
        }
    }

    float4* o4 = reinterpret_cast<float4*>(out) + (size_t)row * (NC / 4);
    #pragma unroll
    for (int q = 0; q < NC / 4; q++) {
        float2 t0 = unpack2(acc[2 * q + 0]);
        float2 t1 = unpack2(acc[2 * q + 1]);
        float4 o;
        o.x = t0.x + __ldg(&b[4 * q + 0]);
        o.y = t0.y + __ldg(&b[4 * q + 1]);
        o.z = t1.x + __ldg(&b[4 * q + 2]);
        o.w = t1.y + __ldg(&b[4 * q + 3]);
        o4[q] = o;
    }
}

extern "C" void kernel_launch(void* const* d_in, const int* in_sizes, int n_in,
                              void* d_out, int out_size)
{
    const float* x        = (const float*)d_in[0];
    const int*   ei       = (const int*)  d_in[1];
    const float* W_in     = (const float*)d_in[2];
    const float* b_in     = (const float*)d_in[3];
    const float* W_layers = (const float*)d_in[4];
    const float* b_layers = (const float*)d_in[5];
    const float* W_cls    = (const float*)d_in[6];
    const float* b_cls    = (const float*)d_in[7];
    float* out = (float*)d_out;

    float *h, *h2, *agg;
    cudaGetSymbolAddress((void**)&h,   g_h);
    cudaGetSymbolAddress((void**)&h2,  g_h2);
    cudaGetSymbolAddress((void**)&agg, g_agg);

    const int gemm_blocks = (Nn + 127) / 128;
    const long long sc_threads = (long long)Ee * 16;
    const int sc_blocks = (int)((sc_threads + 255) / 256);

    gemm_in_kernel<<<gemm_blocks, 128>>>(x, W_in, b_in, h);

    for (int i = 0; i < KL; i++) {
        cudaMemsetAsync(agg, 0, (size_t)Nn * HID * sizeof(float));
        scatter_kernel<<<sc_blocks, 256>>>(ei, h, agg);
        gemm_hid_kernel<<<gemm_blocks, 128>>>(
            h, agg, W_layers + (size_t)i * HID * HID, b_layers + (size_t)i * HID, h2);
        float* t = h; h = h2; h2 = t;
    }

    gemm_out_kernel<<<gemm_blocks, 128>>>(h, W_cls, b_cls, out);
}